// round 14
// baseline (speedup 1.0000x reference)
#include <cuda_runtime.h>
#include <cuda_bf16.h>
#include <cuda_fp16.h>
#include <math.h>

#define T_ 16
#define B_ 1024
#define F_DIM 512
#define H_ 128
#define L_ 512
#define C_ 100
#define KSPLIT 16
#define NCTA 256

// Scratch (static device globals -- no allocation allowed)
__device__ unsigned g_lp[(size_t)T_ * (L_ / 2) * 128];    // 2 MB  packed leafp pairs
__device__ float g_part[(size_t)KSPLIT * B_ * C_];        // 6.5 MB
__device__ unsigned g_pf[(size_t)B_ * (F_DIM / 2)];       // 1 MB  packed feat pairs
__device__ unsigned g_pw1[(size_t)T_ * (F_DIM / 2) * H_]; // 2 MB  packed W1 pairs
__device__ unsigned g_pw2[(size_t)T_ * (H_ / 2) * L_];    // 2 MB  packed W2 pairs
__device__ unsigned g_bar;                                // grid barrier ticket ctr

__device__ __forceinline__ unsigned pkf(float lo, float hi) {
    __nv_bfloat162 h = __floats2bfloat162_rn(lo, hi);
    return *reinterpret_cast<unsigned*>(&h);
}

__device__ __forceinline__ void mma_bf16(float* d, const unsigned* a, const unsigned* b) {
    asm volatile(
        "mma.sync.aligned.m16n8k16.row.col.f32.bf16.bf16.f32 "
        "{%0,%1,%2,%3}, {%4,%5,%6,%7}, {%8,%9}, {%0,%1,%2,%3};\n"
        : "+f"(d[0]), "+f"(d[1]), "+f"(d[2]), "+f"(d[3])
        : "r"(a[0]), "r"(a[1]), "r"(a[2]), "r"(a[3]), "r"(b[0]), "r"(b[1]));
}

__device__ __forceinline__ void cp16(void* s, const void* g) {
    unsigned sa = (unsigned)__cvta_generic_to_shared(s);
    asm volatile("cp.async.ca.shared.global [%0], [%1], 16;\n" :: "r"(sa), "l"(g));
}
#define CP_COMMIT() asm volatile("cp.async.commit_group;\n")
#define CP_WAIT1()  asm volatile("cp.async.wait_group 1;\n")
#define CP_WAIT0()  asm volatile("cp.async.wait_group 0;\n")

// Ticket-based grid barrier. All NCTA CTAs are co-resident (2/SM x 148 SM >= 256),
// so the spin cannot deadlock. Tickets stay 256-aligned across graph replays
// because every launch executes exactly two barriers (+512 arrivals).
__device__ __forceinline__ void grid_barrier() {
    __syncthreads();
    if (threadIdx.x == 0) {
        __threadfence();
        unsigned my = atomicAdd(&g_bar, 1u);
        unsigned target = (my & ~255u) + 256u;
        while (true) {
            unsigned v = *(volatile unsigned*)&g_bar;
            if ((int)(v - target) >= 0) break;
            __nanosleep(60);
        }
        __threadfence();
    }
    __syncthreads();
}

// ---------------------------------------------------------------------------
// One kernel does everything:
//   prep  : pack feat/W1/W2 (5120 u32/CTA) + leaf softmax (32 rows/CTA,
//           smem-staged -> coalesced u32 stores)            [grid barrier]
//   phase1: h  = relu(feat @ W1 + b1)      -> hA (smem, bf16 pairs)
//   phase2: p  = sigmoid(h @ W2 + b2)      -> ph (smem fp16, shifted nodes)
//   phase3: mu = routing products          -> in-place over ph (bf16 pairs)
//   phase4: part[t] = mu @ leafp[t]        -> g_part         [grid barrier]
//   reduce: out = log(sum_t part / (L*T))  (100 float4/CTA)
// grid (16, 16) = 256 CTAs, 256 threads, 107.5KB smem (2 CTAs/SM).
// ---------------------------------------------------------------------------
#define MS_HA (64 * 68)
#define MS_BS (16 * 136)
#define MS_AS (64 * 20)
#define PH_U32 (64 * 260)
#define PH_STRIDE 520
#define SMEM_BYTES ((MS_HA + 3 * MS_BS + PH_U32) * 4)

__global__ __launch_bounds__(256, 2) void forest_mono(const float* __restrict__ feat,
                                                      const float* __restrict__ W1,
                                                      const float* __restrict__ b1,
                                                      const float* __restrict__ W2,
                                                      const float* __restrict__ b2,
                                                      const float* __restrict__ pi,
                                                      float* __restrict__ out) {
    extern __shared__ unsigned sm[];
    unsigned* hA = sm;                          // [64][68]
    unsigned* Bs0 = sm + MS_HA;                 // [3][16*136]
    unsigned* uni = sm + MS_HA + 3 * MS_BS;     // union: As[3][64*20] / ph
    __half* ph = reinterpret_cast<__half*>(uni);

    const int tid = threadIdx.x;
    const int wid = tid >> 5, lane = tid & 31;
    const int warp_m = wid >> 2, warp_n = wid & 3;   // 2x4 warps, 32x32 tiles
    const int lq = lane >> 2, lr = lane & 3;
    const int t = blockIdx.y;
    const int b0 = blockIdx.x * 64;
    const int cid = blockIdx.y * 16 + blockIdx.x;    // 0..255

    // ================= prep: pack 5120 u32 items (5 uint4 chunks/thread) =====
#pragma unroll
    for (int ii = 0; ii < 5; ii++) {
        const int gchunk = cid * 1280 + ii * 256 + tid;
        const int i0 = gchunk * 4;
        if (i0 < 262144) {                       // feat
            float4 a = *reinterpret_cast<const float4*>(&feat[(size_t)i0 * 2]);
            float4 b = *reinterpret_cast<const float4*>(&feat[(size_t)i0 * 2 + 4]);
            uint4 u;
            u.x = pkf(a.x, a.y); u.y = pkf(a.z, a.w);
            u.z = pkf(b.x, b.y); u.w = pkf(b.z, b.w);
            *reinterpret_cast<uint4*>(&g_pf[i0]) = u;
        } else if (i0 < 786432) {                // W1
            int j = i0 - 262144;
            int tt = j >> 15, rem = j & 32767, f2 = rem >> 7, n = rem & 127;
            const float* base = W1 + ((size_t)tt * F_DIM + 2 * f2) * H_ + n;
            float4 x = *reinterpret_cast<const float4*>(base);
            float4 y = *reinterpret_cast<const float4*>(base + H_);
            uint4 u;
            u.x = pkf(x.x, y.x); u.y = pkf(x.y, y.y);
            u.z = pkf(x.z, y.z); u.w = pkf(x.w, y.w);
            *reinterpret_cast<uint4*>(&g_pw1[j]) = u;
        } else {                                 // W2
            int k = i0 - 786432;
            int tt = k >> 15, h2 = (k >> 9) & 63, l = k & 511;
            const float* base = W2 + ((size_t)tt * H_ + 2 * h2) * L_ + l;
            float4 x = *reinterpret_cast<const float4*>(base);
            float4 y = *reinterpret_cast<const float4*>(base + L_);
            uint4 u;
            u.x = pkf(x.x, y.x); u.y = pkf(x.y, y.y);
            u.z = pkf(x.z, y.z); u.w = pkf(x.w, y.w);
            *reinterpret_cast<uint4*>(&g_pw2[k]) = u;
        }
    }

    // ===== prep: leaf softmax, 32 rows/CTA, staged for coalesced u32 stores ===
    {
        unsigned short* stg = reinterpret_cast<unsigned short*>(Bs0);  // [8][128]
        const int R0 = cid * 32;                 // all 32 rows share tree R0>>9
#pragma unroll 1
        for (int iter = 0; iter < 4; iter++) {
            const int row = R0 + iter * 8 + wid;
            const float* pr = pi + (size_t)row * C_;
            float v[4];
#pragma unroll
            for (int j = 0; j < 4; j++) {
                int c = lane + j * 32;
                v[j] = (c < C_) ? pr[c] : -1e30f;
            }
            float m = fmaxf(fmaxf(v[0], v[1]), fmaxf(v[2], v[3]));
#pragma unroll
            for (int o = 16; o; o >>= 1) m = fmaxf(m, __shfl_xor_sync(0xffffffffu, m, o));
            float e[4];
            float s = 0.0f;
#pragma unroll
            for (int j = 0; j < 4; j++) {
                int c = lane + j * 32;
                e[j] = (c < C_) ? __expf(v[j] - m) : 0.0f;
                s += e[j];
            }
#pragma unroll
            for (int o = 16; o; o >>= 1) s += __shfl_xor_sync(0xffffffffu, s, o);
            float inv = 1.0f / s;
#pragma unroll
            for (int j = 0; j < 4; j++) {
                int c = lane + j * 32;
                __nv_bfloat16 bv = __float2bfloat16((c < C_) ? e[j] * inv : 0.0f);
                stg[wid * 128 + c] = *reinterpret_cast<unsigned short*>(&bv);
            }
            __syncthreads();
            // 8 staged rows = 4 (even,odd) pairs -> 512 coalesced u32 stores
#pragma unroll
            for (int i = 0; i < 2; i++) {
                int e2 = tid + i * 256;
                int p = e2 >> 7, c = e2 & 127;
                unsigned lo = stg[(2 * p) * 128 + c];
                unsigned hi = stg[(2 * p + 1) * 128 + c];
                int l0 = R0 + iter * 8 + 2 * p;
                g_lp[((size_t)(l0 >> 9) * (L_ / 2) + ((l0 & 511) >> 1)) * 128 + c] =
                    lo | (hi << 16);
            }
            __syncthreads();
        }
    }

    grid_barrier();   // packed inputs + leafp visible to all CTAs

    float acc[2][4][4];

    // ================= phase 1: GEMM1 -> hA =================
    {
        const unsigned* pf = g_pf + (size_t)b0 * (F_DIM / 2);
        const unsigned* pw = g_pw1 + (size_t)t * (F_DIM / 2) * H_;
        const float* bb = b1 + (size_t)t * H_;

#pragma unroll
        for (int i = 0; i < 2; i++)
#pragma unroll
            for (int j = 0; j < 4; j++)
#pragma unroll
                for (int q = 0; q < 4; q++) acc[i][j][q] = 0.0f;

        auto issue1 = [&](int kt, int buf) {
            const int kp0 = kt * 16;
            {
                int r = tid >> 2, q = tid & 3;
                cp16(&uni[buf * MS_AS + r * 20 + q * 4],
                     &pf[(size_t)r * (F_DIM / 2) + kp0 + q * 4]);
            }
#pragma unroll
            for (int i = 0; i < 2; i++) {
                int e = tid + i * 256;
                int kp = e >> 5, c4 = e & 31;
                cp16(&Bs0[buf * MS_BS + kp * 136 + c4 * 4],
                     &pw[(size_t)(kp0 + kp) * H_ + c4 * 4]);
            }
            CP_COMMIT();
        };

        issue1(0, 0);
        issue1(1, 1);
#pragma unroll 1
        for (int kt = 0; kt < 16; kt++) {
            const int buf = kt % 3;
            if (kt == 15) { CP_WAIT0(); } else { CP_WAIT1(); }
            __syncthreads();

            const unsigned* As = uni + buf * MS_AS;
            const unsigned* Bs = Bs0 + buf * MS_BS;
#pragma unroll
            for (int kh = 0; kh < 2; kh++) {
                const int kb = kh * 8;
                unsigned afr[2][4], bfr[4][2];
#pragma unroll
                for (int im = 0; im < 2; im++) {
                    int r = warp_m * 32 + im * 16;
                    afr[im][0] = As[(r + lq) * 20 + kb + lr];
                    afr[im][1] = As[(r + 8 + lq) * 20 + kb + lr];
                    afr[im][2] = As[(r + lq) * 20 + kb + 4 + lr];
                    afr[im][3] = As[(r + 8 + lq) * 20 + kb + 4 + lr];
                }
#pragma unroll
                for (int jn = 0; jn < 4; jn++) {
                    int c = warp_n * 32 + jn * 8 + lq;
                    bfr[jn][0] = Bs[(kb + lr) * 136 + c];
                    bfr[jn][1] = Bs[(kb + 4 + lr) * 136 + c];
                }
#pragma unroll
                for (int im = 0; im < 2; im++)
#pragma unroll
                    for (int jn = 0; jn < 4; jn++) mma_bf16(acc[im][jn], afr[im], bfr[jn]);
            }
            if (kt + 2 < 16) issue1(kt + 2, (kt + 2) % 3);
        }

        // epilogue -> hA (warp-private rows, disjoint region: no barrier needed)
#pragma unroll
        for (int im = 0; im < 2; im++) {
#pragma unroll
            for (int half = 0; half < 2; half++) {
                int r = warp_m * 32 + im * 16 + half * 8 + lq;
#pragma unroll
                for (int jn = 0; jn < 4; jn++) {
                    int c = warp_n * 32 + jn * 8 + lr * 2;
                    float x0 = fmaxf(acc[im][jn][half * 2 + 0] + bb[c], 0.0f);
                    float x1 = fmaxf(acc[im][jn][half * 2 + 1] + bb[c + 1], 0.0f);
                    hA[r * 68 + (c >> 1)] = pkf(x0, x1);
                }
            }
        }
        __syncthreads();
    }

    // ================= phase 2: GEMM2 + sigmoid -> ph =================
    {
        const unsigned* pw = g_pw2 + (size_t)t * (H_ / 2) * L_;
        const float* bbt = b2 + (size_t)t * L_;

        auto issue2 = [&](int j, int buf) {
            const int chunk = j >> 2, k0s = j & 3;
            const unsigned* src = pw + (size_t)(k0s * 16) * L_ + chunk * 128;
#pragma unroll
            for (int i = 0; i < 2; i++) {
                int e = tid + i * 256;
                int kp = e >> 5, c4 = e & 31;
                cp16(&Bs0[buf * MS_BS + kp * 136 + c4 * 4], &src[(size_t)kp * L_ + c4 * 4]);
            }
            CP_COMMIT();
        };

        issue2(0, 0);
        issue2(1, 1);
#pragma unroll 1
        for (int j = 0; j < 16; j++) {
            const int chunk = j >> 2, k0s = j & 3, buf = j % 3;
            if (k0s == 0) {
#pragma unroll
                for (int i = 0; i < 2; i++)
#pragma unroll
                    for (int jj = 0; jj < 4; jj++)
#pragma unroll
                        for (int q = 0; q < 4; q++) acc[i][jj][q] = 0.0f;
            }
            if (j == 15) { CP_WAIT0(); } else { CP_WAIT1(); }
            __syncthreads();

            const unsigned* Bs = Bs0 + buf * MS_BS;
#pragma unroll
            for (int kh = 0; kh < 2; kh++) {
                const int kbG = k0s * 16 + kh * 8;
                const int kbB = kh * 8;
                unsigned afr[2][4], bfr[4][2];
#pragma unroll
                for (int im = 0; im < 2; im++) {
                    int r = warp_m * 32 + im * 16;
                    afr[im][0] = hA[(r + lq) * 68 + kbG + lr];
                    afr[im][1] = hA[(r + 8 + lq) * 68 + kbG + lr];
                    afr[im][2] = hA[(r + lq) * 68 + kbG + 4 + lr];
                    afr[im][3] = hA[(r + 8 + lq) * 68 + kbG + 4 + lr];
                }
#pragma unroll
                for (int jn = 0; jn < 4; jn++) {
                    int c = warp_n * 32 + jn * 8 + lq;
                    bfr[jn][0] = Bs[(kbB + lr) * 136 + c];
                    bfr[jn][1] = Bs[(kbB + 4 + lr) * 136 + c];
                }
#pragma unroll
                for (int im = 0; im < 2; im++)
#pragma unroll
                    for (int jn = 0; jn < 4; jn++) mma_bf16(acc[im][jn], afr[im], bfr[jn]);
            }

            if (k0s == 3) {
                const int n0c = chunk * 128;
#pragma unroll
                for (int im = 0; im < 2; im++) {
#pragma unroll
                    for (int half = 0; half < 2; half++) {
                        int r = warp_m * 32 + im * 16 + half * 8 + lq;
#pragma unroll
                        for (int jn = 0; jn < 4; jn++) {
                            int c = warp_n * 32 + jn * 8 + lr * 2;
                            float x0 = 1.0f / (1.0f + __expf(-(acc[im][jn][half * 2 + 0] + bbt[n0c + c])));
                            float x1 = 1.0f / (1.0f + __expf(-(acc[im][jn][half * 2 + 1] + bbt[n0c + c + 1])));
                            // shifted node layout: node n -> slot n+1
                            ph[r * PH_STRIDE + 1 + n0c + c] = __float2half(x0);
                            ph[r * PH_STRIDE + 2 + n0c + c] = __float2half(x1);
                        }
                    }
                }
            }
            if (j + 2 < 16) issue2(j + 2, (j + 2) % 3);
        }
        __syncthreads();
    }

    // ================= phase 3: mu in-place over ph =================
#pragma unroll 1
    for (int i = 0; i < 8; i++) {
        int task = i * 256 + tid;
        int row = task >> 5;
        int s = task & 31;
        int l0 = s << 4;
        const __half* sp = ph + row * PH_STRIDE;

        float pref = 1.0f;
#pragma unroll
        for (int d = 0; d < 5; d++) {
            int slot = (1 << d) + (l0 >> (9 - d));
            float v = __half2float(sp[slot]);
            pref *= ((l0 >> (8 - d)) & 1) ? (1.0f - v) : v;
        }

        float v5 = __half2float(sp[32 + s]);
        float c5[2];
        c5[0] = pref * v5;
        c5[1] = pref - c5[0];

        float2 f6 = __half22float2(*reinterpret_cast<const __half2*>(sp + 64 + 2 * s));
        float c6[4];
        c6[0] = c5[0] * f6.x; c6[1] = c5[0] - c6[0];
        c6[2] = c5[1] * f6.y; c6[3] = c5[1] - c6[2];

        uint2 r7 = *reinterpret_cast<const uint2*>(sp + 128 + 4 * s);
        float2 f7a = __half22float2(*reinterpret_cast<const __half2*>(&r7.x));
        float2 f7b = __half22float2(*reinterpret_cast<const __half2*>(&r7.y));
        float c7[8];
        c7[0] = c6[0] * f7a.x; c7[1] = c6[0] - c7[0];
        c7[2] = c6[1] * f7a.y; c7[3] = c6[1] - c7[2];
        c7[4] = c6[2] * f7b.x; c7[5] = c6[2] - c7[4];
        c7[6] = c6[3] * f7b.y; c7[7] = c6[3] - c7[6];

        uint4 r8 = *reinterpret_cast<const uint4*>(sp + 256 + 8 * s);
        float2 f8a = __half22float2(*reinterpret_cast<const __half2*>(&r8.x));
        float2 f8b = __half22float2(*reinterpret_cast<const __half2*>(&r8.y));
        float2 f8c = __half22float2(*reinterpret_cast<const __half2*>(&r8.z));
        float2 f8d = __half22float2(*reinterpret_cast<const __half2*>(&r8.w));
        float c8[16];
        c8[0]  = c7[0] * f8a.x; c8[1]  = c7[0] - c8[0];
        c8[2]  = c7[1] * f8a.y; c8[3]  = c7[1] - c8[2];
        c8[4]  = c7[2] * f8b.x; c8[5]  = c7[2] - c8[4];
        c8[6]  = c7[3] * f8b.y; c8[7]  = c7[3] - c8[6];
        c8[8]  = c7[4] * f8c.x; c8[9]  = c7[4] - c8[8];
        c8[10] = c7[5] * f8c.y; c8[11] = c7[5] - c8[10];
        c8[12] = c7[6] * f8d.x; c8[13] = c7[6] - c8[12];
        c8[14] = c7[7] * f8d.y; c8[15] = c7[7] - c8[14];

        unsigned w[8];
#pragma unroll
        for (int jj = 0; jj < 8; jj++) w[jj] = pkf(c8[2 * jj], c8[2 * jj + 1]);
        unsigned* rowbuf = uni + row * 260;
        *reinterpret_cast<uint4*>(rowbuf + s * 8) = *reinterpret_cast<uint4*>(&w[0]);
        *reinterpret_cast<uint4*>(rowbuf + s * 8 + 4) = *reinterpret_cast<uint4*>(&w[4]);
    }
    __syncthreads();

    // ================= phase 4: GEMM3 (mu @ leafp) -> g_part =================
    {
        const unsigned* lpb = g_lp + (size_t)t * (L_ / 2) * 128;

#pragma unroll
        for (int i = 0; i < 2; i++)
#pragma unroll
            for (int j = 0; j < 4; j++)
#pragma unroll
                for (int q = 0; q < 4; q++) acc[i][j][q] = 0.0f;

        auto issue3 = [&](int kt, int buf) {
#pragma unroll
            for (int i = 0; i < 2; i++) {
                int e = tid + i * 256;
                int kp = e >> 5, c4 = e & 31;
                cp16(&Bs0[buf * MS_BS + kp * 136 + c4 * 4],
                     &lpb[(size_t)(kt * 16 + kp) * 128 + c4 * 4]);
            }
            CP_COMMIT();
        };

        issue3(0, 0);
        issue3(1, 1);
#pragma unroll 1
        for (int kt = 0; kt < 16; kt++) {
            const int buf = kt % 3;
            if (kt == 15) { CP_WAIT0(); } else { CP_WAIT1(); }
            __syncthreads();

            const unsigned* Bs = Bs0 + buf * MS_BS;
#pragma unroll
            for (int kh = 0; kh < 2; kh++) {
                const int kbA = kt * 16 + kh * 8;   // A pair base (mu in smem)
                const int kbB = kh * 8;
                unsigned afr[2][4], bfr[4][2];
#pragma unroll
                for (int im = 0; im < 2; im++) {
                    int r = warp_m * 32 + im * 16;
                    afr[im][0] = uni[(r + lq) * 260 + kbA + lr];
                    afr[im][1] = uni[(r + 8 + lq) * 260 + kbA + lr];
                    afr[im][2] = uni[(r + lq) * 260 + kbA + 4 + lr];
                    afr[im][3] = uni[(r + 8 + lq) * 260 + kbA + 4 + lr];
                }
#pragma unroll
                for (int jn = 0; jn < 4; jn++) {
                    int c = warp_n * 32 + jn * 8 + lq;
                    bfr[jn][0] = Bs[(kbB + lr) * 136 + c];
                    bfr[jn][1] = Bs[(kbB + 4 + lr) * 136 + c];
                }
#pragma unroll
                for (int im = 0; im < 2; im++)
#pragma unroll
                    for (int jn = 0; jn < 4; jn++) mma_bf16(acc[im][jn], afr[im], bfr[jn]);
            }
            if (kt + 2 < 16) issue3(kt + 2, (kt + 2) % 3);
        }

        float* pb = g_part + (size_t)t * B_ * C_;
#pragma unroll
        for (int im = 0; im < 2; im++) {
#pragma unroll
            for (int half = 0; half < 2; half++) {
                int r = warp_m * 32 + im * 16 + half * 8 + lq;
#pragma unroll
                for (int jn = 0; jn < 4; jn++) {
                    int c = warp_n * 32 + jn * 8 + lr * 2;
                    if (c >= C_) continue;
                    *reinterpret_cast<float2*>(&pb[(size_t)(b0 + r) * C_ + c]) =
                        make_float2(acc[im][jn][half * 2 + 0], acc[im][jn][half * 2 + 1]);
                }
            }
        }
    }

    grid_barrier();   // all partials written

    // ================= reduce + log: 100 float4 per CTA =================
    if (tid < 100) {
        const int c = (cid * 100 + tid) * 4;
        float4 s = make_float4(0.f, 0.f, 0.f, 0.f);
#pragma unroll
        for (int ks = 0; ks < KSPLIT; ks++) {
            float4 v = *reinterpret_cast<const float4*>(&g_part[(size_t)ks * B_ * C_ + c]);
            s.x += v.x; s.y += v.y; s.z += v.z; s.w += v.w;
        }
        const float sc = 1.0f / (float)(L_ * T_);
        float4 r;
        r.x = logf(s.x * sc); r.y = logf(s.y * sc);
        r.z = logf(s.z * sc); r.w = logf(s.w * sc);
        *reinterpret_cast<float4*>(&out[c]) = r;
    }
}

extern "C" void kernel_launch(void* const* d_in, const int* in_sizes, int n_in,
                              void* d_out, int out_size) {
    const float* feat = (const float*)d_in[0];
    const float* W1 = (const float*)d_in[1];
    const float* b1 = (const float*)d_in[2];
    const float* W2 = (const float*)d_in[3];
    const float* b2 = (const float*)d_in[4];
    const float* pi = (const float*)d_in[5];
    float* out = (float*)d_out;

    cudaFuncSetAttribute(forest_mono, cudaFuncAttributeMaxDynamicSharedMemorySize, SMEM_BYTES);

    forest_mono<<<dim3(B_ / 64, T_), 256, SMEM_BYTES>>>(feat, W1, b1, W2, b2, pi, out);
}

// round 15
// speedup vs baseline: 1.0045x; 1.0045x over previous
#include <cuda_runtime.h>
#include <cuda_bf16.h>
#include <cuda_fp16.h>
#include <math.h>

#define T_ 16
#define B_ 1024
#define F_DIM 512
#define H_ 128
#define L_ 512
#define C_ 100
#define KSPLIT 16

// Scratch (static device globals -- no allocation allowed)
__device__ unsigned g_lp[(size_t)T_ * (L_ / 2) * 128];    // 2 MB  packed leafp pairs
__device__ float g_part[(size_t)KSPLIT * B_ * C_];        // 6.5 MB
__device__ unsigned g_pf[(size_t)B_ * (F_DIM / 2)];       // 1 MB  packed feat pairs
__device__ unsigned g_pw1[(size_t)T_ * (F_DIM / 2) * H_]; // 2 MB  packed W1 pairs
__device__ unsigned g_pw2[(size_t)T_ * (H_ / 2) * L_];    // 2 MB  packed W2 pairs

__device__ __forceinline__ unsigned pkf(float lo, float hi) {
    __nv_bfloat162 h = __floats2bfloat162_rn(lo, hi);
    return *reinterpret_cast<unsigned*>(&h);
}

__device__ __forceinline__ void mma_bf16(float* d, const unsigned* a, const unsigned* b) {
    asm volatile(
        "mma.sync.aligned.m16n8k16.row.col.f32.bf16.bf16.f32 "
        "{%0,%1,%2,%3}, {%4,%5,%6,%7}, {%8,%9}, {%0,%1,%2,%3};\n"
        : "+f"(d[0]), "+f"(d[1]), "+f"(d[2]), "+f"(d[3])
        : "r"(a[0]), "r"(a[1]), "r"(a[2]), "r"(a[3]), "r"(b[0]), "r"(b[1]));
}

__device__ __forceinline__ void cp16(void* s, const void* g) {
    unsigned sa = (unsigned)__cvta_generic_to_shared(s);
    asm volatile("cp.async.ca.shared.global [%0], [%1], 16;\n" :: "r"(sa), "l"(g));
}
#define CP_COMMIT() asm volatile("cp.async.commit_group;\n")
#define CP_WAIT1()  asm volatile("cp.async.wait_group 1;\n")
#define CP_WAIT0()  asm volatile("cp.async.wait_group 0;\n")

// ---------------------------------------------------------------------------
// Merged prep:
//   bx [0,256)    : pack feat  (4 u32 items/thread)
//   bx [256,768)  : pack W1
//   bx [768,1280) : pack W2
//   bx [1280,1536): leaf softmax, 32 rows/block, smem-staged ->
//                   fully coalesced u32 stores into the packed g_lp layout
// ---------------------------------------------------------------------------
__global__ __launch_bounds__(256) void prep_kernel(const float* __restrict__ feat,
                                                   const float* __restrict__ W1,
                                                   const float* __restrict__ W2,
                                                   const float* __restrict__ pi) {
    __shared__ unsigned short stg[8 * 128];
    const int bx = blockIdx.x;
    const int tid = threadIdx.x;
    if (bx < 256) {
        const int i = (bx * 256 + tid) * 4;
        float4 a = *reinterpret_cast<const float4*>(&feat[(size_t)i * 2]);
        float4 b = *reinterpret_cast<const float4*>(&feat[(size_t)i * 2 + 4]);
        uint4 u;
        u.x = pkf(a.x, a.y); u.y = pkf(a.z, a.w);
        u.z = pkf(b.x, b.y); u.w = pkf(b.z, b.w);
        *reinterpret_cast<uint4*>(&g_pf[i]) = u;
    } else if (bx < 768) {
        const int i = ((bx - 256) * 256 + tid) * 4;
        int t = i >> 15, rem = i & 32767, f2 = rem >> 7, n = rem & 127;  // n % 4 == 0
        const float* base = W1 + ((size_t)t * F_DIM + 2 * f2) * H_ + n;
        float4 x = *reinterpret_cast<const float4*>(base);
        float4 y = *reinterpret_cast<const float4*>(base + H_);
        uint4 u;
        u.x = pkf(x.x, y.x); u.y = pkf(x.y, y.y);
        u.z = pkf(x.z, y.z); u.w = pkf(x.w, y.w);
        *reinterpret_cast<uint4*>(&g_pw1[i]) = u;
    } else if (bx < 1280) {
        const int i = ((bx - 768) * 256 + tid) * 4;
        int t = i >> 15, h2 = (i >> 9) & 63, l = i & 511;  // l % 4 == 0
        const float* base = W2 + ((size_t)t * H_ + 2 * h2) * L_ + l;
        float4 x = *reinterpret_cast<const float4*>(base);
        float4 y = *reinterpret_cast<const float4*>(base + L_);
        uint4 u;
        u.x = pkf(x.x, y.x); u.y = pkf(x.y, y.y);
        u.z = pkf(x.z, y.z); u.w = pkf(x.w, y.w);
        *reinterpret_cast<uint4*>(&g_pw2[i]) = u;
    } else {
        // softmax: 32 consecutive rows (all within one tree), staged in smem.
        const int wid = tid >> 5, lane = tid & 31;
        const int R0 = (bx - 1280) * 32;
#pragma unroll 1
        for (int iter = 0; iter < 4; iter++) {
            const int row = R0 + iter * 8 + wid;
            const float* pr = pi + (size_t)row * C_;
            float v[4];
#pragma unroll
            for (int j = 0; j < 4; j++) {
                int c = lane + j * 32;
                v[j] = (c < C_) ? pr[c] : -1e30f;
            }
            float m = fmaxf(fmaxf(v[0], v[1]), fmaxf(v[2], v[3]));
#pragma unroll
            for (int o = 16; o; o >>= 1) m = fmaxf(m, __shfl_xor_sync(0xffffffffu, m, o));
            float e[4];
            float s = 0.0f;
#pragma unroll
            for (int j = 0; j < 4; j++) {
                int c = lane + j * 32;
                e[j] = (c < C_) ? __expf(v[j] - m) : 0.0f;
                s += e[j];
            }
#pragma unroll
            for (int o = 16; o; o >>= 1) s += __shfl_xor_sync(0xffffffffu, s, o);
            float inv = 1.0f / s;
#pragma unroll
            for (int j = 0; j < 4; j++) {
                int c = lane + j * 32;
                __nv_bfloat16 bv = __float2bfloat16((c < C_) ? e[j] * inv : 0.0f);
                stg[wid * 128 + c] = *reinterpret_cast<unsigned short*>(&bv);
            }
            __syncthreads();
            // 8 staged rows = 4 (even,odd) row-pairs -> 512 coalesced u32 stores
#pragma unroll
            for (int i = 0; i < 2; i++) {
                int e2 = tid + i * 256;
                int p = e2 >> 7, c = e2 & 127;
                unsigned lo = stg[(2 * p) * 128 + c];
                unsigned hi = stg[(2 * p + 1) * 128 + c];
                int l0 = R0 + iter * 8 + 2 * p;
                g_lp[((size_t)(l0 >> 9) * (L_ / 2) + ((l0 & 511) >> 1)) * 128 + c] =
                    lo | (hi << 16);
            }
            __syncthreads();
        }
    }
}

// ---------------------------------------------------------------------------
// Fully fused per-(tree, 64-row) kernel, 3-stage cp.async, ONE sync per tile.
// Bs stride 136 (mod 32 = 8 -> banks 8*lr+lq, all 32 distinct: conflict-free).
// grid (B/64, T) = 256 CTAs, 256 threads, 107.5KB smem (2 CTAs/SM).
// ---------------------------------------------------------------------------
#define MS_HA (64 * 68)
#define MS_BS (16 * 136)
#define MS_AS (64 * 20)
#define PH_U32 (64 * 260)
#define PH_STRIDE 520
#define SMEM_BYTES ((MS_HA + 3 * MS_BS + PH_U32) * 4)

__global__ __launch_bounds__(256, 2) void forest_fused(const float* __restrict__ b1,
                                                       const float* __restrict__ b2) {
    extern __shared__ unsigned sm[];
    unsigned* hA = sm;                          // [64][68]
    unsigned* Bs0 = sm + MS_HA;                 // [3][16*136]
    unsigned* uni = sm + MS_HA + 3 * MS_BS;     // union: As[3][64*20] / ph
    __half* ph = reinterpret_cast<__half*>(uni);

    const int tid = threadIdx.x;
    const int wid = tid >> 5, lane = tid & 31;
    const int warp_m = wid >> 2, warp_n = wid & 3;   // 2x4 warps, 32x32 tiles
    const int lq = lane >> 2, lr = lane & 3;
    const int t = blockIdx.y;
    const int b0 = blockIdx.x * 64;

    float acc[2][4][4];

    // ================= phase 1: GEMM1 -> hA =================
    {
        const unsigned* pf = g_pf + (size_t)b0 * (F_DIM / 2);
        const unsigned* pw = g_pw1 + (size_t)t * (F_DIM / 2) * H_;
        const float* bb = b1 + (size_t)t * H_;

#pragma unroll
        for (int i = 0; i < 2; i++)
#pragma unroll
            for (int j = 0; j < 4; j++)
#pragma unroll
                for (int q = 0; q < 4; q++) acc[i][j][q] = 0.0f;

        auto issue1 = [&](int kt, int buf) {
            const int kp0 = kt * 16;
            {
                int r = tid >> 2, q = tid & 3;
                cp16(&uni[buf * MS_AS + r * 20 + q * 4],
                     &pf[(size_t)r * (F_DIM / 2) + kp0 + q * 4]);
            }
#pragma unroll
            for (int i = 0; i < 2; i++) {
                int e = tid + i * 256;
                int kp = e >> 5, c4 = e & 31;
                cp16(&Bs0[buf * MS_BS + kp * 136 + c4 * 4],
                     &pw[(size_t)(kp0 + kp) * H_ + c4 * 4]);
            }
            CP_COMMIT();
        };

        issue1(0, 0);
        issue1(1, 1);
#pragma unroll 1
        for (int kt = 0; kt < 16; kt++) {
            const int buf = kt % 3;
            if (kt == 15) { CP_WAIT0(); } else { CP_WAIT1(); }
            __syncthreads();

            const unsigned* As = uni + buf * MS_AS;
            const unsigned* Bs = Bs0 + buf * MS_BS;
#pragma unroll
            for (int kh = 0; kh < 2; kh++) {
                const int kb = kh * 8;
                unsigned afr[2][4], bfr[4][2];
#pragma unroll
                for (int im = 0; im < 2; im++) {
                    int r = warp_m * 32 + im * 16;
                    afr[im][0] = As[(r + lq) * 20 + kb + lr];
                    afr[im][1] = As[(r + 8 + lq) * 20 + kb + lr];
                    afr[im][2] = As[(r + lq) * 20 + kb + 4 + lr];
                    afr[im][3] = As[(r + 8 + lq) * 20 + kb + 4 + lr];
                }
#pragma unroll
                for (int jn = 0; jn < 4; jn++) {
                    int c = warp_n * 32 + jn * 8 + lq;
                    bfr[jn][0] = Bs[(kb + lr) * 136 + c];
                    bfr[jn][1] = Bs[(kb + 4 + lr) * 136 + c];
                }
#pragma unroll
                for (int im = 0; im < 2; im++)
#pragma unroll
                    for (int jn = 0; jn < 4; jn++) mma_bf16(acc[im][jn], afr[im], bfr[jn]);
            }
            if (kt + 2 < 16) issue1(kt + 2, (kt + 2) % 3);
        }

        // epilogue -> hA (warp-private rows, disjoint region: no barrier needed)
#pragma unroll
        for (int im = 0; im < 2; im++) {
#pragma unroll
            for (int half = 0; half < 2; half++) {
                int r = warp_m * 32 + im * 16 + half * 8 + lq;
#pragma unroll
                for (int jn = 0; jn < 4; jn++) {
                    int c = warp_n * 32 + jn * 8 + lr * 2;
                    float x0 = fmaxf(acc[im][jn][half * 2 + 0] + bb[c], 0.0f);
                    float x1 = fmaxf(acc[im][jn][half * 2 + 1] + bb[c + 1], 0.0f);
                    hA[r * 68 + (c >> 1)] = pkf(x0, x1);
                }
            }
        }
        __syncthreads();
    }

    // ================= phase 2: GEMM2 + sigmoid -> ph =================
    {
        const unsigned* pw = g_pw2 + (size_t)t * (H_ / 2) * L_;
        const float* bbt = b2 + (size_t)t * L_;

        auto issue2 = [&](int j, int buf) {
            const int chunk = j >> 2, k0s = j & 3;
            const unsigned* src = pw + (size_t)(k0s * 16) * L_ + chunk * 128;
#pragma unroll
            for (int i = 0; i < 2; i++) {
                int e = tid + i * 256;
                int kp = e >> 5, c4 = e & 31;
                cp16(&Bs0[buf * MS_BS + kp * 136 + c4 * 4], &src[(size_t)kp * L_ + c4 * 4]);
            }
            CP_COMMIT();
        };

        issue2(0, 0);
        issue2(1, 1);
#pragma unroll 1
        for (int j = 0; j < 16; j++) {
            const int chunk = j >> 2, k0s = j & 3, buf = j % 3;
            if (k0s == 0) {
#pragma unroll
                for (int i = 0; i < 2; i++)
#pragma unroll
                    for (int jj = 0; jj < 4; jj++)
#pragma unroll
                        for (int q = 0; q < 4; q++) acc[i][jj][q] = 0.0f;
            }
            if (j == 15) { CP_WAIT0(); } else { CP_WAIT1(); }
            __syncthreads();

            const unsigned* Bs = Bs0 + buf * MS_BS;
#pragma unroll
            for (int kh = 0; kh < 2; kh++) {
                const int kbG = k0s * 16 + kh * 8;
                const int kbB = kh * 8;
                unsigned afr[2][4], bfr[4][2];
#pragma unroll
                for (int im = 0; im < 2; im++) {
                    int r = warp_m * 32 + im * 16;
                    afr[im][0] = hA[(r + lq) * 68 + kbG + lr];
                    afr[im][1] = hA[(r + 8 + lq) * 68 + kbG + lr];
                    afr[im][2] = hA[(r + lq) * 68 + kbG + 4 + lr];
                    afr[im][3] = hA[(r + 8 + lq) * 68 + kbG + 4 + lr];
                }
#pragma unroll
                for (int jn = 0; jn < 4; jn++) {
                    int c = warp_n * 32 + jn * 8 + lq;
                    bfr[jn][0] = Bs[(kbB + lr) * 136 + c];
                    bfr[jn][1] = Bs[(kbB + 4 + lr) * 136 + c];
                }
#pragma unroll
                for (int im = 0; im < 2; im++)
#pragma unroll
                    for (int jn = 0; jn < 4; jn++) mma_bf16(acc[im][jn], afr[im], bfr[jn]);
            }

            if (k0s == 3) {
                const int n0c = chunk * 128;
#pragma unroll
                for (int im = 0; im < 2; im++) {
#pragma unroll
                    for (int half = 0; half < 2; half++) {
                        int r = warp_m * 32 + im * 16 + half * 8 + lq;
#pragma unroll
                        for (int jn = 0; jn < 4; jn++) {
                            int c = warp_n * 32 + jn * 8 + lr * 2;
                            float x0 = 1.0f / (1.0f + __expf(-(acc[im][jn][half * 2 + 0] + bbt[n0c + c])));
                            float x1 = 1.0f / (1.0f + __expf(-(acc[im][jn][half * 2 + 1] + bbt[n0c + c + 1])));
                            // shifted node layout: node n -> slot n+1
                            ph[r * PH_STRIDE + 1 + n0c + c] = __float2half(x0);
                            ph[r * PH_STRIDE + 2 + n0c + c] = __float2half(x1);
                        }
                    }
                }
            }
            if (j + 2 < 16) issue2(j + 2, (j + 2) % 3);
        }
        __syncthreads();
    }

    // ================= phase 3: mu in-place over ph =================
#pragma unroll 1
    for (int i = 0; i < 8; i++) {
        int task = i * 256 + tid;
        int row = task >> 5;
        int s = task & 31;
        int l0 = s << 4;
        const __half* sp = ph + row * PH_STRIDE;

        float pref = 1.0f;
#pragma unroll
        for (int d = 0; d < 5; d++) {
            int slot = (1 << d) + (l0 >> (9 - d));
            float v = __half2float(sp[slot]);
            pref *= ((l0 >> (8 - d)) & 1) ? (1.0f - v) : v;
        }

        float v5 = __half2float(sp[32 + s]);
        float c5[2];
        c5[0] = pref * v5;
        c5[1] = pref - c5[0];

        float2 f6 = __half22float2(*reinterpret_cast<const __half2*>(sp + 64 + 2 * s));
        float c6[4];
        c6[0] = c5[0] * f6.x; c6[1] = c5[0] - c6[0];
        c6[2] = c5[1] * f6.y; c6[3] = c5[1] - c6[2];

        uint2 r7 = *reinterpret_cast<const uint2*>(sp + 128 + 4 * s);
        float2 f7a = __half22float2(*reinterpret_cast<const __half2*>(&r7.x));
        float2 f7b = __half22float2(*reinterpret_cast<const __half2*>(&r7.y));
        float c7[8];
        c7[0] = c6[0] * f7a.x; c7[1] = c6[0] - c7[0];
        c7[2] = c6[1] * f7a.y; c7[3] = c6[1] - c7[2];
        c7[4] = c6[2] * f7b.x; c7[5] = c6[2] - c7[4];
        c7[6] = c6[3] * f7b.y; c7[7] = c6[3] - c7[6];

        uint4 r8 = *reinterpret_cast<const uint4*>(sp + 256 + 8 * s);
        float2 f8a = __half22float2(*reinterpret_cast<const __half2*>(&r8.x));
        float2 f8b = __half22float2(*reinterpret_cast<const __half2*>(&r8.y));
        float2 f8c = __half22float2(*reinterpret_cast<const __half2*>(&r8.z));
        float2 f8d = __half22float2(*reinterpret_cast<const __half2*>(&r8.w));
        float c8[16];
        c8[0]  = c7[0] * f8a.x; c8[1]  = c7[0] - c8[0];
        c8[2]  = c7[1] * f8a.y; c8[3]  = c7[1] - c8[2];
        c8[4]  = c7[2] * f8b.x; c8[5]  = c7[2] - c8[4];
        c8[6]  = c7[3] * f8b.y; c8[7]  = c7[3] - c8[6];
        c8[8]  = c7[4] * f8c.x; c8[9]  = c7[4] - c8[8];
        c8[10] = c7[5] * f8c.y; c8[11] = c7[5] - c8[10];
        c8[12] = c7[6] * f8d.x; c8[13] = c7[6] - c8[12];
        c8[14] = c7[7] * f8d.y; c8[15] = c7[7] - c8[14];

        unsigned w[8];
#pragma unroll
        for (int jj = 0; jj < 8; jj++) w[jj] = pkf(c8[2 * jj], c8[2 * jj + 1]);
        unsigned* rowbuf = uni + row * 260;
        *reinterpret_cast<uint4*>(rowbuf + s * 8) = *reinterpret_cast<uint4*>(&w[0]);
        *reinterpret_cast<uint4*>(rowbuf + s * 8 + 4) = *reinterpret_cast<uint4*>(&w[4]);
    }
    __syncthreads();

    // ================= phase 4: GEMM3 (mu @ leafp) -> g_part =================
    {
        const unsigned* lpb = g_lp + (size_t)t * (L_ / 2) * 128;

#pragma unroll
        for (int i = 0; i < 2; i++)
#pragma unroll
            for (int j = 0; j < 4; j++)
#pragma unroll
                for (int q = 0; q < 4; q++) acc[i][j][q] = 0.0f;

        auto issue3 = [&](int kt, int buf) {
#pragma unroll
            for (int i = 0; i < 2; i++) {
                int e = tid + i * 256;
                int kp = e >> 5, c4 = e & 31;
                cp16(&Bs0[buf * MS_BS + kp * 136 + c4 * 4],
                     &lpb[(size_t)(kt * 16 + kp) * 128 + c4 * 4]);
            }
            CP_COMMIT();
        };

        issue3(0, 0);
        issue3(1, 1);
#pragma unroll 1
        for (int kt = 0; kt < 16; kt++) {
            const int buf = kt % 3;
            if (kt == 15) { CP_WAIT0(); } else { CP_WAIT1(); }
            __syncthreads();

            const unsigned* Bs = Bs0 + buf * MS_BS;
#pragma unroll
            for (int kh = 0; kh < 2; kh++) {
                const int kbA = kt * 16 + kh * 8;   // A pair base (mu in smem)
                const int kbB = kh * 8;
                unsigned afr[2][4], bfr[4][2];
#pragma unroll
                for (int im = 0; im < 2; im++) {
                    int r = warp_m * 32 + im * 16;
                    afr[im][0] = uni[(r + lq) * 260 + kbA + lr];
                    afr[im][1] = uni[(r + 8 + lq) * 260 + kbA + lr];
                    afr[im][2] = uni[(r + lq) * 260 + kbA + 4 + lr];
                    afr[im][3] = uni[(r + 8 + lq) * 260 + kbA + 4 + lr];
                }
#pragma unroll
                for (int jn = 0; jn < 4; jn++) {
                    int c = warp_n * 32 + jn * 8 + lq;
                    bfr[jn][0] = Bs[(kbB + lr) * 136 + c];
                    bfr[jn][1] = Bs[(kbB + 4 + lr) * 136 + c];
                }
#pragma unroll
                for (int im = 0; im < 2; im++)
#pragma unroll
                    for (int jn = 0; jn < 4; jn++) mma_bf16(acc[im][jn], afr[im], bfr[jn]);
            }
            if (kt + 2 < 16) issue3(kt + 2, (kt + 2) % 3);
        }

        float* pb = g_part + (size_t)t * B_ * C_;
#pragma unroll
        for (int im = 0; im < 2; im++) {
#pragma unroll
            for (int half = 0; half < 2; half++) {
                int r = warp_m * 32 + im * 16 + half * 8 + lq;
#pragma unroll
                for (int jn = 0; jn < 4; jn++) {
                    int c = warp_n * 32 + jn * 8 + lr * 2;
                    if (c >= C_) continue;
                    *reinterpret_cast<float2*>(&pb[(size_t)(b0 + r) * C_ + c]) =
                        make_float2(acc[im][jn][half * 2 + 0], acc[im][jn][half * 2 + 1]);
                }
            }
        }
    }
}

// ---------------------------------------------------------------------------
// Deterministic reduction over trees + final log, float4-vectorized.
// ---------------------------------------------------------------------------
__global__ __launch_bounds__(256) void reduce_log_kernel(float* __restrict__ out) {
    const int c = (blockIdx.x * 256 + threadIdx.x) * 4;   // 0 .. B*C-4
    float4 s = make_float4(0.f, 0.f, 0.f, 0.f);
#pragma unroll
    for (int ks = 0; ks < KSPLIT; ks++) {
        float4 v = *reinterpret_cast<const float4*>(&g_part[(size_t)ks * B_ * C_ + c]);
        s.x += v.x; s.y += v.y; s.z += v.z; s.w += v.w;
    }
    const float sc = 1.0f / (float)(L_ * T_);
    float4 r;
    r.x = logf(s.x * sc); r.y = logf(s.y * sc);
    r.z = logf(s.z * sc); r.w = logf(s.w * sc);
    *reinterpret_cast<float4*>(&out[c]) = r;
}

extern "C" void kernel_launch(void* const* d_in, const int* in_sizes, int n_in,
                              void* d_out, int out_size) {
    const float* feat = (const float*)d_in[0];
    const float* W1 = (const float*)d_in[1];
    const float* b1 = (const float*)d_in[2];
    const float* W2 = (const float*)d_in[3];
    const float* b2 = (const float*)d_in[4];
    const float* pi = (const float*)d_in[5];
    float* out = (float*)d_out;

    cudaFuncSetAttribute(forest_fused, cudaFuncAttributeMaxDynamicSharedMemorySize, SMEM_BYTES);

    prep_kernel<<<1536, 256>>>(feat, W1, W2, pi);
    forest_fused<<<dim3(B_ / 64, T_), 256, SMEM_BYTES>>>(b1, b2);
    reduce_log_kernel<<<(B_ * C_) / 1024, 256>>>(out);
}

// round 16
// speedup vs baseline: 1.0293x; 1.0247x over previous
#include <cuda_runtime.h>
#include <cuda_bf16.h>
#include <cuda_fp16.h>
#include <math.h>

#define T_ 16
#define B_ 1024
#define F_DIM 512
#define H_ 128
#define L_ 512
#define C_ 100
#define KSPLIT 16

// Scratch (static device globals -- no allocation allowed)
__device__ unsigned g_lp[(size_t)T_ * (L_ / 2) * 128];    // 2 MB  packed leafp pairs
__device__ float g_part[(size_t)KSPLIT * B_ * C_];        // 6.5 MB
__device__ unsigned g_pf[(size_t)B_ * (F_DIM / 2)];       // 1 MB  packed feat pairs
__device__ unsigned g_pw1[(size_t)T_ * (F_DIM / 2) * H_]; // 2 MB  packed W1 pairs
__device__ unsigned g_pw2[(size_t)T_ * (H_ / 2) * L_];    // 2 MB  packed W2 pairs

__device__ __forceinline__ unsigned pkf(float lo, float hi) {
    __nv_bfloat162 h = __floats2bfloat162_rn(lo, hi);
    return *reinterpret_cast<unsigned*>(&h);
}

__device__ __forceinline__ void mma_bf16(float* d, const unsigned* a, const unsigned* b) {
    asm volatile(
        "mma.sync.aligned.m16n8k16.row.col.f32.bf16.bf16.f32 "
        "{%0,%1,%2,%3}, {%4,%5,%6,%7}, {%8,%9}, {%0,%1,%2,%3};\n"
        : "+f"(d[0]), "+f"(d[1]), "+f"(d[2]), "+f"(d[3])
        : "r"(a[0]), "r"(a[1]), "r"(a[2]), "r"(a[3]), "r"(b[0]), "r"(b[1]));
}

__device__ __forceinline__ void cp16(void* s, const void* g) {
    unsigned sa = (unsigned)__cvta_generic_to_shared(s);
    asm volatile("cp.async.ca.shared.global [%0], [%1], 16;\n" :: "r"(sa), "l"(g));
}
#define CP_COMMIT() asm volatile("cp.async.commit_group;\n")
#define CP_WAIT1()  asm volatile("cp.async.wait_group 1;\n")
#define CP_WAIT0()  asm volatile("cp.async.wait_group 0;\n")

// ---------------------------------------------------------------------------
// Merged prep, 4 items/thread (R12 measured-best: 6.9us):
//   bx [0,256)    : pack feat   (256K u32 items)
//   bx [256,768)  : pack W1     (512K u32 items)
//   bx [768,1280) : pack W2     (512K u32 items)
//   bx [1280,2304): leaf softmax (8 rows/block, one warp per row)
// ---------------------------------------------------------------------------
__global__ __launch_bounds__(256) void prep_kernel(const float* __restrict__ feat,
                                                   const float* __restrict__ W1,
                                                   const float* __restrict__ W2,
                                                   const float* __restrict__ pi) {
    const int bx = blockIdx.x;
    const int tid = threadIdx.x;
    if (bx < 256) {
        const int i = (bx * 256 + tid) * 4;
        float4 a = *reinterpret_cast<const float4*>(&feat[(size_t)i * 2]);
        float4 b = *reinterpret_cast<const float4*>(&feat[(size_t)i * 2 + 4]);
        uint4 u;
        u.x = pkf(a.x, a.y); u.y = pkf(a.z, a.w);
        u.z = pkf(b.x, b.y); u.w = pkf(b.z, b.w);
        *reinterpret_cast<uint4*>(&g_pf[i]) = u;
    } else if (bx < 768) {
        const int i = ((bx - 256) * 256 + tid) * 4;
        int t = i >> 15, rem = i & 32767, f2 = rem >> 7, n = rem & 127;  // n % 4 == 0
        const float* base = W1 + ((size_t)t * F_DIM + 2 * f2) * H_ + n;
        float4 x = *reinterpret_cast<const float4*>(base);
        float4 y = *reinterpret_cast<const float4*>(base + H_);
        uint4 u;
        u.x = pkf(x.x, y.x); u.y = pkf(x.y, y.y);
        u.z = pkf(x.z, y.z); u.w = pkf(x.w, y.w);
        *reinterpret_cast<uint4*>(&g_pw1[i]) = u;
    } else if (bx < 1280) {
        const int i = ((bx - 768) * 256 + tid) * 4;
        int t = i >> 15, h2 = (i >> 9) & 63, l = i & 511;  // l % 4 == 0
        const float* base = W2 + ((size_t)t * H_ + 2 * h2) * L_ + l;
        float4 x = *reinterpret_cast<const float4*>(base);
        float4 y = *reinterpret_cast<const float4*>(base + L_);
        uint4 u;
        u.x = pkf(x.x, y.x); u.y = pkf(x.y, y.y);
        u.z = pkf(x.z, y.z); u.w = pkf(x.w, y.w);
        *reinterpret_cast<uint4*>(&g_pw2[i]) = u;
    } else {
        // softmax: 8 warps/block, one (t,l) row each
        const int row = (bx - 1280) * 8 + (tid >> 5);   // t*L + l
        const int lane = tid & 31;
        const int t = row >> 9, l = row & (L_ - 1);
        const float* pr = pi + (size_t)row * C_;

        float v[4];
#pragma unroll
        for (int j = 0; j < 4; j++) {
            int c = lane + j * 32;
            v[j] = (c < C_) ? pr[c] : -1e30f;
        }
        float m = fmaxf(fmaxf(v[0], v[1]), fmaxf(v[2], v[3]));
#pragma unroll
        for (int o = 16; o; o >>= 1) m = fmaxf(m, __shfl_xor_sync(0xffffffffu, m, o));

        float e[4];
        float s = 0.0f;
#pragma unroll
        for (int j = 0; j < 4; j++) {
            int c = lane + j * 32;
            e[j] = (c < C_) ? __expf(v[j] - m) : 0.0f;
            s += e[j];
        }
#pragma unroll
        for (int o = 16; o; o >>= 1) s += __shfl_xor_sync(0xffffffffu, s, o);
        float inv = 1.0f / s;

        unsigned short* base = reinterpret_cast<unsigned short*>(g_lp);
        const size_t rowbase = ((size_t)t * (L_ / 2) + (l >> 1)) * 128;
#pragma unroll
        for (int j = 0; j < 4; j++) {
            int c = lane + j * 32;
            __nv_bfloat16 bv = __float2bfloat16((c < C_) ? e[j] * inv : 0.0f);
            base[(rowbase + c) * 2 + (l & 1)] = *reinterpret_cast<unsigned short*>(&bv);
        }
    }
}

// ---------------------------------------------------------------------------
// Fully fused per-(tree, 64-row) kernel, 3-stage cp.async, ONE sync per tile.
// Bs stride 136 (mod 32 = 8 -> banks 8*lr+lq, all 32 distinct: conflict-free).
// grid (B/64, T) = 256 CTAs, 256 threads, 107.5KB smem (2 CTAs/SM).
// ---------------------------------------------------------------------------
#define MS_HA (64 * 68)
#define MS_BS (16 * 136)
#define MS_AS (64 * 20)
#define PH_U32 (64 * 260)
#define PH_STRIDE 520
#define SMEM_BYTES ((MS_HA + 3 * MS_BS + PH_U32) * 4)

__global__ __launch_bounds__(256, 2) void forest_fused(const float* __restrict__ b1,
                                                       const float* __restrict__ b2) {
    extern __shared__ unsigned sm[];
    unsigned* hA = sm;                          // [64][68]
    unsigned* Bs0 = sm + MS_HA;                 // [3][16*136]
    unsigned* uni = sm + MS_HA + 3 * MS_BS;     // union: As[3][64*20] / ph
    __half* ph = reinterpret_cast<__half*>(uni);

    const int tid = threadIdx.x;
    const int wid = tid >> 5, lane = tid & 31;
    const int warp_m = wid >> 2, warp_n = wid & 3;   // 2x4 warps, 32x32 tiles
    const int lq = lane >> 2, lr = lane & 3;
    const int t = blockIdx.y;
    const int b0 = blockIdx.x * 64;

    float acc[2][4][4];

    // ================= phase 1: GEMM1 -> hA =================
    {
        const unsigned* pf = g_pf + (size_t)b0 * (F_DIM / 2);
        const unsigned* pw = g_pw1 + (size_t)t * (F_DIM / 2) * H_;
        const float* bb = b1 + (size_t)t * H_;

#pragma unroll
        for (int i = 0; i < 2; i++)
#pragma unroll
            for (int j = 0; j < 4; j++)
#pragma unroll
                for (int q = 0; q < 4; q++) acc[i][j][q] = 0.0f;

        auto issue1 = [&](int kt, int buf) {
            const int kp0 = kt * 16;
            {
                int r = tid >> 2, q = tid & 3;
                cp16(&uni[buf * MS_AS + r * 20 + q * 4],
                     &pf[(size_t)r * (F_DIM / 2) + kp0 + q * 4]);
            }
#pragma unroll
            for (int i = 0; i < 2; i++) {
                int e = tid + i * 256;
                int kp = e >> 5, c4 = e & 31;
                cp16(&Bs0[buf * MS_BS + kp * 136 + c4 * 4],
                     &pw[(size_t)(kp0 + kp) * H_ + c4 * 4]);
            }
            CP_COMMIT();
        };

        issue1(0, 0);
        issue1(1, 1);
#pragma unroll 1
        for (int kt = 0; kt < 16; kt++) {
            const int buf = kt % 3;
            if (kt == 15) { CP_WAIT0(); } else { CP_WAIT1(); }
            __syncthreads();

            const unsigned* As = uni + buf * MS_AS;
            const unsigned* Bs = Bs0 + buf * MS_BS;
#pragma unroll
            for (int kh = 0; kh < 2; kh++) {
                const int kb = kh * 8;
                unsigned afr[2][4], bfr[4][2];
#pragma unroll
                for (int im = 0; im < 2; im++) {
                    int r = warp_m * 32 + im * 16;
                    afr[im][0] = As[(r + lq) * 20 + kb + lr];
                    afr[im][1] = As[(r + 8 + lq) * 20 + kb + lr];
                    afr[im][2] = As[(r + lq) * 20 + kb + 4 + lr];
                    afr[im][3] = As[(r + 8 + lq) * 20 + kb + 4 + lr];
                }
#pragma unroll
                for (int jn = 0; jn < 4; jn++) {
                    int c = warp_n * 32 + jn * 8 + lq;
                    bfr[jn][0] = Bs[(kb + lr) * 136 + c];
                    bfr[jn][1] = Bs[(kb + 4 + lr) * 136 + c];
                }
#pragma unroll
                for (int im = 0; im < 2; im++)
#pragma unroll
                    for (int jn = 0; jn < 4; jn++) mma_bf16(acc[im][jn], afr[im], bfr[jn]);
            }
            if (kt + 2 < 16) issue1(kt + 2, (kt + 2) % 3);
        }

        // epilogue -> hA (warp-private rows, disjoint region: no barrier needed)
#pragma unroll
        for (int im = 0; im < 2; im++) {
#pragma unroll
            for (int half = 0; half < 2; half++) {
                int r = warp_m * 32 + im * 16 + half * 8 + lq;
#pragma unroll
                for (int jn = 0; jn < 4; jn++) {
                    int c = warp_n * 32 + jn * 8 + lr * 2;
                    float x0 = fmaxf(acc[im][jn][half * 2 + 0] + bb[c], 0.0f);
                    float x1 = fmaxf(acc[im][jn][half * 2 + 1] + bb[c + 1], 0.0f);
                    hA[r * 68 + (c >> 1)] = pkf(x0, x1);
                }
            }
        }
        __syncthreads();
    }

    // ================= phase 2: GEMM2 + sigmoid -> ph =================
    {
        const unsigned* pw = g_pw2 + (size_t)t * (H_ / 2) * L_;
        const float* bbt = b2 + (size_t)t * L_;

        auto issue2 = [&](int j, int buf) {
            const int chunk = j >> 2, k0s = j & 3;
            const unsigned* src = pw + (size_t)(k0s * 16) * L_ + chunk * 128;
#pragma unroll
            for (int i = 0; i < 2; i++) {
                int e = tid + i * 256;
                int kp = e >> 5, c4 = e & 31;
                cp16(&Bs0[buf * MS_BS + kp * 136 + c4 * 4], &src[(size_t)kp * L_ + c4 * 4]);
            }
            CP_COMMIT();
        };

        issue2(0, 0);
        issue2(1, 1);
#pragma unroll 1
        for (int j = 0; j < 16; j++) {
            const int chunk = j >> 2, k0s = j & 3, buf = j % 3;
            if (k0s == 0) {
#pragma unroll
                for (int i = 0; i < 2; i++)
#pragma unroll
                    for (int jj = 0; jj < 4; jj++)
#pragma unroll
                        for (int q = 0; q < 4; q++) acc[i][jj][q] = 0.0f;
            }
            if (j == 15) { CP_WAIT0(); } else { CP_WAIT1(); }
            __syncthreads();

            const unsigned* Bs = Bs0 + buf * MS_BS;
#pragma unroll
            for (int kh = 0; kh < 2; kh++) {
                const int kbG = k0s * 16 + kh * 8;
                const int kbB = kh * 8;
                unsigned afr[2][4], bfr[4][2];
#pragma unroll
                for (int im = 0; im < 2; im++) {
                    int r = warp_m * 32 + im * 16;
                    afr[im][0] = hA[(r + lq) * 68 + kbG + lr];
                    afr[im][1] = hA[(r + 8 + lq) * 68 + kbG + lr];
                    afr[im][2] = hA[(r + lq) * 68 + kbG + 4 + lr];
                    afr[im][3] = hA[(r + 8 + lq) * 68 + kbG + 4 + lr];
                }
#pragma unroll
                for (int jn = 0; jn < 4; jn++) {
                    int c = warp_n * 32 + jn * 8 + lq;
                    bfr[jn][0] = Bs[(kbB + lr) * 136 + c];
                    bfr[jn][1] = Bs[(kbB + 4 + lr) * 136 + c];
                }
#pragma unroll
                for (int im = 0; im < 2; im++)
#pragma unroll
                    for (int jn = 0; jn < 4; jn++) mma_bf16(acc[im][jn], afr[im], bfr[jn]);
            }

            if (k0s == 3) {
                const int n0c = chunk * 128;
#pragma unroll
                for (int im = 0; im < 2; im++) {
#pragma unroll
                    for (int half = 0; half < 2; half++) {
                        int r = warp_m * 32 + im * 16 + half * 8 + lq;
#pragma unroll
                        for (int jn = 0; jn < 4; jn++) {
                            int c = warp_n * 32 + jn * 8 + lr * 2;
                            float x0 = 1.0f / (1.0f + __expf(-(acc[im][jn][half * 2 + 0] + bbt[n0c + c])));
                            float x1 = 1.0f / (1.0f + __expf(-(acc[im][jn][half * 2 + 1] + bbt[n0c + c + 1])));
                            // shifted node layout: node n -> slot n+1
                            ph[r * PH_STRIDE + 1 + n0c + c] = __float2half(x0);
                            ph[r * PH_STRIDE + 2 + n0c + c] = __float2half(x1);
                        }
                    }
                }
            }
            if (j + 2 < 16) issue2(j + 2, (j + 2) % 3);
        }
        __syncthreads();
    }

    // ================= phase 3: mu in-place over ph =================
#pragma unroll 1
    for (int i = 0; i < 8; i++) {
        int task = i * 256 + tid;
        int row = task >> 5;
        int s = task & 31;
        int l0 = s << 4;
        const __half* sp = ph + row * PH_STRIDE;

        float pref = 1.0f;
#pragma unroll
        for (int d = 0; d < 5; d++) {
            int slot = (1 << d) + (l0 >> (9 - d));
            float v = __half2float(sp[slot]);
            pref *= ((l0 >> (8 - d)) & 1) ? (1.0f - v) : v;
        }

        float v5 = __half2float(sp[32 + s]);
        float c5[2];
        c5[0] = pref * v5;
        c5[1] = pref - c5[0];

        float2 f6 = __half22float2(*reinterpret_cast<const __half2*>(sp + 64 + 2 * s));
        float c6[4];
        c6[0] = c5[0] * f6.x; c6[1] = c5[0] - c6[0];
        c6[2] = c5[1] * f6.y; c6[3] = c5[1] - c6[2];

        uint2 r7 = *reinterpret_cast<const uint2*>(sp + 128 + 4 * s);
        float2 f7a = __half22float2(*reinterpret_cast<const __half2*>(&r7.x));
        float2 f7b = __half22float2(*reinterpret_cast<const __half2*>(&r7.y));
        float c7[8];
        c7[0] = c6[0] * f7a.x; c7[1] = c6[0] - c7[0];
        c7[2] = c6[1] * f7a.y; c7[3] = c6[1] - c7[2];
        c7[4] = c6[2] * f7b.x; c7[5] = c6[2] - c7[4];
        c7[6] = c6[3] * f7b.y; c7[7] = c6[3] - c7[6];

        uint4 r8 = *reinterpret_cast<const uint4*>(sp + 256 + 8 * s);
        float2 f8a = __half22float2(*reinterpret_cast<const __half2*>(&r8.x));
        float2 f8b = __half22float2(*reinterpret_cast<const __half2*>(&r8.y));
        float2 f8c = __half22float2(*reinterpret_cast<const __half2*>(&r8.z));
        float2 f8d = __half22float2(*reinterpret_cast<const __half2*>(&r8.w));
        float c8[16];
        c8[0]  = c7[0] * f8a.x; c8[1]  = c7[0] - c8[0];
        c8[2]  = c7[1] * f8a.y; c8[3]  = c7[1] - c8[2];
        c8[4]  = c7[2] * f8b.x; c8[5]  = c7[2] - c8[4];
        c8[6]  = c7[3] * f8b.y; c8[7]  = c7[3] - c8[6];
        c8[8]  = c7[4] * f8c.x; c8[9]  = c7[4] - c8[8];
        c8[10] = c7[5] * f8c.y; c8[11] = c7[5] - c8[10];
        c8[12] = c7[6] * f8d.x; c8[13] = c7[6] - c8[12];
        c8[14] = c7[7] * f8d.y; c8[15] = c7[7] - c8[14];

        unsigned w[8];
#pragma unroll
        for (int jj = 0; jj < 8; jj++) w[jj] = pkf(c8[2 * jj], c8[2 * jj + 1]);
        unsigned* rowbuf = uni + row * 260;
        *reinterpret_cast<uint4*>(rowbuf + s * 8) = *reinterpret_cast<uint4*>(&w[0]);
        *reinterpret_cast<uint4*>(rowbuf + s * 8 + 4) = *reinterpret_cast<uint4*>(&w[4]);
    }
    __syncthreads();

    // ================= phase 4: GEMM3 (mu @ leafp) -> g_part =================
    {
        const unsigned* lpb = g_lp + (size_t)t * (L_ / 2) * 128;

#pragma unroll
        for (int i = 0; i < 2; i++)
#pragma unroll
            for (int j = 0; j < 4; j++)
#pragma unroll
                for (int q = 0; q < 4; q++) acc[i][j][q] = 0.0f;

        auto issue3 = [&](int kt, int buf) {
#pragma unroll
            for (int i = 0; i < 2; i++) {
                int e = tid + i * 256;
                int kp = e >> 5, c4 = e & 31;
                cp16(&Bs0[buf * MS_BS + kp * 136 + c4 * 4],
                     &lpb[(size_t)(kt * 16 + kp) * 128 + c4 * 4]);
            }
            CP_COMMIT();
        };

        issue3(0, 0);
        issue3(1, 1);
#pragma unroll 1
        for (int kt = 0; kt < 16; kt++) {
            const int buf = kt % 3;
            if (kt == 15) { CP_WAIT0(); } else { CP_WAIT1(); }
            __syncthreads();

            const unsigned* Bs = Bs0 + buf * MS_BS;
#pragma unroll
            for (int kh = 0; kh < 2; kh++) {
                const int kbA = kt * 16 + kh * 8;   // A pair base (mu in smem)
                const int kbB = kh * 8;
                unsigned afr[2][4], bfr[4][2];
#pragma unroll
                for (int im = 0; im < 2; im++) {
                    int r = warp_m * 32 + im * 16;
                    afr[im][0] = uni[(r + lq) * 260 + kbA + lr];
                    afr[im][1] = uni[(r + 8 + lq) * 260 + kbA + lr];
                    afr[im][2] = uni[(r + lq) * 260 + kbA + 4 + lr];
                    afr[im][3] = uni[(r + 8 + lq) * 260 + kbA + 4 + lr];
                }
#pragma unroll
                for (int jn = 0; jn < 4; jn++) {
                    int c = warp_n * 32 + jn * 8 + lq;
                    bfr[jn][0] = Bs[(kbB + lr) * 136 + c];
                    bfr[jn][1] = Bs[(kbB + 4 + lr) * 136 + c];
                }
#pragma unroll
                for (int im = 0; im < 2; im++)
#pragma unroll
                    for (int jn = 0; jn < 4; jn++) mma_bf16(acc[im][jn], afr[im], bfr[jn]);
            }
            if (kt + 2 < 16) issue3(kt + 2, (kt + 2) % 3);
        }

        float* pb = g_part + (size_t)t * B_ * C_;
#pragma unroll
        for (int im = 0; im < 2; im++) {
#pragma unroll
            for (int half = 0; half < 2; half++) {
                int r = warp_m * 32 + im * 16 + half * 8 + lq;
#pragma unroll
                for (int jn = 0; jn < 4; jn++) {
                    int c = warp_n * 32 + jn * 8 + lr * 2;
                    if (c >= C_) continue;
                    *reinterpret_cast<float2*>(&pb[(size_t)(b0 + r) * C_ + c]) =
                        make_float2(acc[im][jn][half * 2 + 0], acc[im][jn][half * 2 + 1]);
                }
            }
        }
    }
}

// ---------------------------------------------------------------------------
// Deterministic reduction over trees + final log, float4-vectorized.
// ---------------------------------------------------------------------------
__global__ __launch_bounds__(256) void reduce_log_kernel(float* __restrict__ out) {
    const int c = (blockIdx.x * 256 + threadIdx.x) * 4;   // 0 .. B*C-4
    float4 s = make_float4(0.f, 0.f, 0.f, 0.f);
#pragma unroll
    for (int ks = 0; ks < KSPLIT; ks++) {
        float4 v = *reinterpret_cast<const float4*>(&g_part[(size_t)ks * B_ * C_ + c]);
        s.x += v.x; s.y += v.y; s.z += v.z; s.w += v.w;
    }
    const float sc = 1.0f / (float)(L_ * T_);
    float4 r;
    r.x = logf(s.x * sc); r.y = logf(s.y * sc);
    r.z = logf(s.z * sc); r.w = logf(s.w * sc);
    *reinterpret_cast<float4*>(&out[c]) = r;
}

extern "C" void kernel_launch(void* const* d_in, const int* in_sizes, int n_in,
                              void* d_out, int out_size) {
    const float* feat = (const float*)d_in[0];
    const float* W1 = (const float*)d_in[1];
    const float* b1 = (const float*)d_in[2];
    const float* W2 = (const float*)d_in[3];
    const float* b2 = (const float*)d_in[4];
    const float* pi = (const float*)d_in[5];
    float* out = (float*)d_out;

    cudaFuncSetAttribute(forest_fused, cudaFuncAttributeMaxDynamicSharedMemorySize, SMEM_BYTES);

    prep_kernel<<<2304, 256>>>(feat, W1, W2, pi);
    forest_fused<<<dim3(B_ / 64, T_), 256, SMEM_BYTES>>>(b1, b2);
    reduce_log_kernel<<<(B_ * C_) / 1024, 256>>>(out);
}

// round 17
// speedup vs baseline: 1.0628x; 1.0326x over previous
#include <cuda_runtime.h>
#include <cuda_bf16.h>
#include <cuda_fp16.h>
#include <math.h>

#define T_ 16
#define B_ 1024
#define F_DIM 512
#define H_ 128
#define L_ 512
#define C_ 100
#define KSPLIT 16

// Scratch (static device globals -- no allocation allowed)
__device__ unsigned g_lp[(size_t)T_ * L_ * 64];           // 2 MB  leafp bf16 rows [t*L+l][128 cols]
__device__ float g_part[(size_t)KSPLIT * B_ * C_];        // 6.5 MB
__device__ unsigned g_pf[(size_t)B_ * (F_DIM / 2)];       // 1 MB  packed feat pairs (A layout)
__device__ unsigned g_pw1[(size_t)T_ * F_DIM * (H_ / 2)]; // 2 MB  W1 bf16 rows [k][n]
__device__ unsigned g_pw2[(size_t)T_ * H_ * (L_ / 2)];    // 2 MB  W2 bf16 rows [k][n]

__device__ __forceinline__ unsigned pkf(float lo, float hi) {
    __nv_bfloat162 h = __floats2bfloat162_rn(lo, hi);
    return *reinterpret_cast<unsigned*>(&h);
}

__device__ __forceinline__ void mma_bf16(float* d, const unsigned* a, const unsigned* b) {
    asm volatile(
        "mma.sync.aligned.m16n8k16.row.col.f32.bf16.bf16.f32 "
        "{%0,%1,%2,%3}, {%4,%5,%6,%7}, {%8,%9}, {%0,%1,%2,%3};\n"
        : "+f"(d[0]), "+f"(d[1]), "+f"(d[2]), "+f"(d[3])
        : "r"(a[0]), "r"(a[1]), "r"(a[2]), "r"(a[3]), "r"(b[0]), "r"(b[1]));
}

__device__ __forceinline__ void ldsm4(unsigned* r, unsigned saddr) {
    asm volatile("ldmatrix.sync.aligned.m8n8.x4.shared.b16 {%0,%1,%2,%3}, [%4];\n"
                 : "=r"(r[0]), "=r"(r[1]), "=r"(r[2]), "=r"(r[3]) : "r"(saddr));
}
__device__ __forceinline__ void ldsm4t(unsigned* r, unsigned saddr) {
    asm volatile("ldmatrix.sync.aligned.m8n8.x4.trans.shared.b16 {%0,%1,%2,%3}, [%4];\n"
                 : "=r"(r[0]), "=r"(r[1]), "=r"(r[2]), "=r"(r[3]) : "r"(saddr));
}

__device__ __forceinline__ void cp16(void* s, const void* g) {
    unsigned sa = (unsigned)__cvta_generic_to_shared(s);
    asm volatile("cp.async.ca.shared.global [%0], [%1], 16;\n" :: "r"(sa), "l"(g));
}
#define CP_COMMIT() asm volatile("cp.async.commit_group;\n")
#define CP_WAIT1()  asm volatile("cp.async.wait_group 1;\n")
#define CP_WAIT0()  asm volatile("cp.async.wait_group 0;\n")

// ---------------------------------------------------------------------------
// Merged prep, 4 u32 items/thread:
//   bx [0,256)    : pack feat  (pair layout, 256K items)
//   bx [256,768)  : pack W1    (plain bf16 stream, 512K items)
//   bx [768,1280) : pack W2    (plain bf16 stream, 512K items)
//   bx [1280,2304): leaf softmax (8 rows/block, one warp per row, uint2 out)
// ---------------------------------------------------------------------------
__global__ __launch_bounds__(256) void prep_kernel(const float* __restrict__ feat,
                                                   const float* __restrict__ W1,
                                                   const float* __restrict__ W2,
                                                   const float* __restrict__ pi) {
    const int bx = blockIdx.x;
    const int tid = threadIdx.x;
    if (bx < 256) {
        const int i = (bx * 256 + tid) * 4;
        float4 a = *reinterpret_cast<const float4*>(&feat[(size_t)i * 2]);
        float4 b = *reinterpret_cast<const float4*>(&feat[(size_t)i * 2 + 4]);
        uint4 u;
        u.x = pkf(a.x, a.y); u.y = pkf(a.z, a.w);
        u.z = pkf(b.x, b.y); u.w = pkf(b.z, b.w);
        *reinterpret_cast<uint4*>(&g_pf[i]) = u;
    } else if (bx < 768) {
        const int i = ((bx - 256) * 256 + tid) * 4;
        float4 a = *reinterpret_cast<const float4*>(&W1[(size_t)i * 2]);
        float4 b = *reinterpret_cast<const float4*>(&W1[(size_t)i * 2 + 4]);
        uint4 u;
        u.x = pkf(a.x, a.y); u.y = pkf(a.z, a.w);
        u.z = pkf(b.x, b.y); u.w = pkf(b.z, b.w);
        *reinterpret_cast<uint4*>(&g_pw1[i]) = u;
    } else if (bx < 1280) {
        const int i = ((bx - 768) * 256 + tid) * 4;
        float4 a = *reinterpret_cast<const float4*>(&W2[(size_t)i * 2]);
        float4 b = *reinterpret_cast<const float4*>(&W2[(size_t)i * 2 + 4]);
        uint4 u;
        u.x = pkf(a.x, a.y); u.y = pkf(a.z, a.w);
        u.z = pkf(b.x, b.y); u.w = pkf(b.z, b.w);
        *reinterpret_cast<uint4*>(&g_pw2[i]) = u;
    } else {
        // softmax: 8 warps/block, one (t,l) row each; lane covers cols 4l..4l+3
        const int row = (bx - 1280) * 8 + (tid >> 5);   // t*L + l
        const int lane = tid & 31;
        const float* pr = pi + (size_t)row * C_;

        float4 v = make_float4(-1e30f, -1e30f, -1e30f, -1e30f);
        if (lane < 25) v = *reinterpret_cast<const float4*>(&pr[lane * 4]);
        float m = fmaxf(fmaxf(v.x, v.y), fmaxf(v.z, v.w));
#pragma unroll
        for (int o = 16; o; o >>= 1) m = fmaxf(m, __shfl_xor_sync(0xffffffffu, m, o));

        float e0 = 0.f, e1 = 0.f, e2 = 0.f, e3 = 0.f;
        if (lane < 25) {
            e0 = __expf(v.x - m); e1 = __expf(v.y - m);
            e2 = __expf(v.z - m); e3 = __expf(v.w - m);
        }
        float s = e0 + e1 + e2 + e3;
#pragma unroll
        for (int o = 16; o; o >>= 1) s += __shfl_xor_sync(0xffffffffu, s, o);
        float inv = 1.0f / s;

        uint2 w = make_uint2(0u, 0u);
        if (lane < 25) {
            w.x = pkf(e0 * inv, e1 * inv);
            w.y = pkf(e2 * inv, e3 * inv);
        }
        *reinterpret_cast<uint2*>(&g_lp[(size_t)row * 64 + lane * 2]) = w;
    }
}

// ---------------------------------------------------------------------------
// Fully fused per-(tree, 64-row) kernel, 3-stage cp.async, ONE sync per tile.
// Fragment loads via ldmatrix (A non-trans from pair layout, B trans from
// k-major bf16 rows, stride 68 u32 -> bank-group (r+c)%8, conflict-free).
// grid (B/64, T) = 256 CTAs, 256 threads, 107.5KB smem (2 CTAs/SM).
// ---------------------------------------------------------------------------
#define MS_HA (64 * 68)
#define MS_BS (32 * 68)
#define MS_AS (64 * 20)
#define PH_U32 (64 * 260)
#define PH_STRIDE 520
#define SMEM_BYTES ((MS_HA + 3 * MS_BS + PH_U32) * 4)

__global__ __launch_bounds__(256, 2) void forest_fused(const float* __restrict__ b1,
                                                       const float* __restrict__ b2) {
    extern __shared__ unsigned sm[];
    unsigned* hA = sm;                          // [64][68]  h pairs
    unsigned* Bs0 = sm + MS_HA;                 // [3][32*68] bf16 k-major rows
    unsigned* uni = sm + MS_HA + 3 * MS_BS;     // union: As[3][64*20] / ph
    __half* ph = reinterpret_cast<__half*>(uni);

    const int tid = threadIdx.x;
    const int wid = tid >> 5, lane = tid & 31;
    const int warp_m = wid >> 2, warp_n = wid & 3;   // 2x4 warps, 32x32 tiles
    const int lq = lane >> 2, lr = lane & 3;
    const int t = blockIdx.y;
    const int b0 = blockIdx.x * 64;

    // ldmatrix lane geometry
    const int arow = ((lane >> 3) & 1) * 8 + (lane & 7);   // A row within 16
    const int apcol = ((lane >> 4) & 1) * 4;               // A pair col 0/4
    const int bkrow = ((lane >> 3) & 1) * 8 + (lane & 7);  // B k-row within 16
    const int bncol = warp_n * 32 + ((lane >> 4) & 1) * 8; // B b16 col (q=0)

    const unsigned s_uni = (unsigned)__cvta_generic_to_shared(uni);
    const unsigned s_bs = (unsigned)__cvta_generic_to_shared(Bs0);
    const unsigned s_hA = (unsigned)__cvta_generic_to_shared(hA);

    float acc[2][4][4];

    // ================= phase 1: GEMM1 -> hA =================
    {
        const unsigned* pf = g_pf + (size_t)b0 * (F_DIM / 2);
        const unsigned* pw = g_pw1 + (size_t)t * F_DIM * (H_ / 2);
        const float* bb = b1 + (size_t)t * H_;

#pragma unroll
        for (int i = 0; i < 2; i++)
#pragma unroll
            for (int j = 0; j < 4; j++)
#pragma unroll
                for (int q = 0; q < 4; q++) acc[i][j][q] = 0.0f;

        auto issue1 = [&](int kt, int buf) {
            const int kp0 = kt * 16;
            {   // A: 64 rows x 4 chunks (pair layout)
                int r = tid >> 2, q = tid & 3;
                cp16(&uni[buf * MS_AS + r * 20 + q * 4],
                     &pf[(size_t)r * (F_DIM / 2) + kp0 + q * 4]);
            }
            // B: 32 k-rows x 16 chunks (bf16 rows, global stride 64 u32)
#pragma unroll
            for (int i = 0; i < 2; i++) {
                int e = tid + i * 256;
                int row = e >> 4, ch = e & 15;
                cp16(&Bs0[buf * MS_BS + row * 68 + ch * 4],
                     &pw[(size_t)(kt * 32 + row) * 64 + ch * 4]);
            }
            CP_COMMIT();
        };

        issue1(0, 0);
        issue1(1, 1);
#pragma unroll 1
        for (int kt = 0; kt < 16; kt++) {
            const int buf = kt % 3;
            if (kt == 15) { CP_WAIT0(); } else { CP_WAIT1(); }
            __syncthreads();

#pragma unroll
            for (int kh = 0; kh < 2; kh++) {
                const int kb = kh * 8;
                unsigned a0[4], a1[4], bA[4], bB[4];
                unsigned sa = s_uni + (buf * MS_AS + (warp_m * 32 + arow) * 20 + kb + apcol) * 4;
                ldsm4(a0, sa);
                ldsm4(a1, sa + 16 * 20 * 4);
                unsigned sb = s_bs + (buf * MS_BS + (kh * 16 + bkrow) * 68) * 4 + bncol * 2;
                ldsm4t(bA, sb);
                ldsm4t(bB, sb + 32);
                mma_bf16(acc[0][0], a0, bA); mma_bf16(acc[0][1], a0, bA + 2);
                mma_bf16(acc[0][2], a0, bB); mma_bf16(acc[0][3], a0, bB + 2);
                mma_bf16(acc[1][0], a1, bA); mma_bf16(acc[1][1], a1, bA + 2);
                mma_bf16(acc[1][2], a1, bB); mma_bf16(acc[1][3], a1, bB + 2);
            }
            if (kt + 2 < 16) issue1(kt + 2, (kt + 2) % 3);
        }

        // epilogue -> hA (warp-private rows, disjoint region: no barrier needed)
#pragma unroll
        for (int im = 0; im < 2; im++) {
#pragma unroll
            for (int half = 0; half < 2; half++) {
                int r = warp_m * 32 + im * 16 + half * 8 + lq;
#pragma unroll
                for (int jn = 0; jn < 4; jn++) {
                    int c = warp_n * 32 + jn * 8 + lr * 2;
                    float x0 = fmaxf(acc[im][jn][half * 2 + 0] + bb[c], 0.0f);
                    float x1 = fmaxf(acc[im][jn][half * 2 + 1] + bb[c + 1], 0.0f);
                    hA[r * 68 + (c >> 1)] = pkf(x0, x1);
                }
            }
        }
        __syncthreads();
    }

    // ================= phase 2: GEMM2 + sigmoid -> ph =================
    {
        const unsigned* pw = g_pw2 + (size_t)t * H_ * (L_ / 2);
        const float* bbt = b2 + (size_t)t * L_;

        auto issue2 = [&](int j, int buf) {
            const int chunk = j >> 2, k0s = j & 3;
            const unsigned* src = pw + (size_t)(k0s * 32) * 256 + chunk * 64;
#pragma unroll
            for (int i = 0; i < 2; i++) {
                int e = tid + i * 256;
                int row = e >> 4, ch = e & 15;
                cp16(&Bs0[buf * MS_BS + row * 68 + ch * 4], &src[(size_t)row * 256 + ch * 4]);
            }
            CP_COMMIT();
        };

        issue2(0, 0);
        issue2(1, 1);
#pragma unroll 1
        for (int j = 0; j < 16; j++) {
            const int chunk = j >> 2, k0s = j & 3, buf = j % 3;
            if (k0s == 0) {
#pragma unroll
                for (int i = 0; i < 2; i++)
#pragma unroll
                    for (int jj = 0; jj < 4; jj++)
#pragma unroll
                        for (int q = 0; q < 4; q++) acc[i][jj][q] = 0.0f;
            }
            if (j == 15) { CP_WAIT0(); } else { CP_WAIT1(); }
            __syncthreads();

#pragma unroll
            for (int kh = 0; kh < 2; kh++) {
                const int kbG = k0s * 16 + kh * 8;
                unsigned a0[4], a1[4], bA[4], bB[4];
                unsigned sa = s_hA + ((warp_m * 32 + arow) * 68 + kbG + apcol) * 4;
                ldsm4(a0, sa);
                ldsm4(a1, sa + 16 * 68 * 4);
                unsigned sb = s_bs + (buf * MS_BS + (kh * 16 + bkrow) * 68) * 4 + bncol * 2;
                ldsm4t(bA, sb);
                ldsm4t(bB, sb + 32);
                mma_bf16(acc[0][0], a0, bA); mma_bf16(acc[0][1], a0, bA + 2);
                mma_bf16(acc[0][2], a0, bB); mma_bf16(acc[0][3], a0, bB + 2);
                mma_bf16(acc[1][0], a1, bA); mma_bf16(acc[1][1], a1, bA + 2);
                mma_bf16(acc[1][2], a1, bB); mma_bf16(acc[1][3], a1, bB + 2);
            }

            if (k0s == 3) {
                const int n0c = chunk * 128;
#pragma unroll
                for (int im = 0; im < 2; im++) {
#pragma unroll
                    for (int half = 0; half < 2; half++) {
                        int r = warp_m * 32 + im * 16 + half * 8 + lq;
#pragma unroll
                        for (int jn = 0; jn < 4; jn++) {
                            int c = warp_n * 32 + jn * 8 + lr * 2;
                            float x0 = 1.0f / (1.0f + __expf(-(acc[im][jn][half * 2 + 0] + bbt[n0c + c])));
                            float x1 = 1.0f / (1.0f + __expf(-(acc[im][jn][half * 2 + 1] + bbt[n0c + c + 1])));
                            // shifted node layout: node n -> slot n+1
                            ph[r * PH_STRIDE + 1 + n0c + c] = __float2half(x0);
                            ph[r * PH_STRIDE + 2 + n0c + c] = __float2half(x1);
                        }
                    }
                }
            }
            if (j + 2 < 16) issue2(j + 2, (j + 2) % 3);
        }
        __syncthreads();
    }

    // ================= phase 3: mu in-place over ph =================
#pragma unroll 1
    for (int i = 0; i < 8; i++) {
        int task = i * 256 + tid;
        int row = task >> 5;
        int s = task & 31;
        int l0 = s << 4;
        const __half* sp = ph + row * PH_STRIDE;

        float pref = 1.0f;
#pragma unroll
        for (int d = 0; d < 5; d++) {
            int slot = (1 << d) + (l0 >> (9 - d));
            float v = __half2float(sp[slot]);
            pref *= ((l0 >> (8 - d)) & 1) ? (1.0f - v) : v;
        }

        float v5 = __half2float(sp[32 + s]);
        float c5[2];
        c5[0] = pref * v5;
        c5[1] = pref - c5[0];

        float2 f6 = __half22float2(*reinterpret_cast<const __half2*>(sp + 64 + 2 * s));
        float c6[4];
        c6[0] = c5[0] * f6.x; c6[1] = c5[0] - c6[0];
        c6[2] = c5[1] * f6.y; c6[3] = c5[1] - c6[2];

        uint2 r7 = *reinterpret_cast<const uint2*>(sp + 128 + 4 * s);
        float2 f7a = __half22float2(*reinterpret_cast<const __half2*>(&r7.x));
        float2 f7b = __half22float2(*reinterpret_cast<const __half2*>(&r7.y));
        float c7[8];
        c7[0] = c6[0] * f7a.x; c7[1] = c6[0] - c7[0];
        c7[2] = c6[1] * f7a.y; c7[3] = c6[1] - c7[2];
        c7[4] = c6[2] * f7b.x; c7[5] = c6[2] - c7[4];
        c7[6] = c6[3] * f7b.y; c7[7] = c6[3] - c7[6];

        uint4 r8 = *reinterpret_cast<const uint4*>(sp + 256 + 8 * s);
        float2 f8a = __half22float2(*reinterpret_cast<const __half2*>(&r8.x));
        float2 f8b = __half22float2(*reinterpret_cast<const __half2*>(&r8.y));
        float2 f8c = __half22float2(*reinterpret_cast<const __half2*>(&r8.z));
        float2 f8d = __half22float2(*reinterpret_cast<const __half2*>(&r8.w));
        float c8[16];
        c8[0]  = c7[0] * f8a.x; c8[1]  = c7[0] - c8[0];
        c8[2]  = c7[1] * f8a.y; c8[3]  = c7[1] - c8[2];
        c8[4]  = c7[2] * f8b.x; c8[5]  = c7[2] - c8[4];
        c8[6]  = c7[3] * f8b.y; c8[7]  = c7[3] - c8[6];
        c8[8]  = c7[4] * f8c.x; c8[9]  = c7[4] - c8[8];
        c8[10] = c7[5] * f8c.y; c8[11] = c7[5] - c8[10];
        c8[12] = c7[6] * f8d.x; c8[13] = c7[6] - c8[12];
        c8[14] = c7[7] * f8d.y; c8[15] = c7[7] - c8[14];

        unsigned w[8];
#pragma unroll
        for (int jj = 0; jj < 8; jj++) w[jj] = pkf(c8[2 * jj], c8[2 * jj + 1]);
        unsigned* rowbuf = uni + row * 260;
        *reinterpret_cast<uint4*>(rowbuf + s * 8) = *reinterpret_cast<uint4*>(&w[0]);
        *reinterpret_cast<uint4*>(rowbuf + s * 8 + 4) = *reinterpret_cast<uint4*>(&w[4]);
    }
    __syncthreads();

    // ================= phase 4: GEMM3 (mu @ leafp) -> g_part =================
    {
        const unsigned* lpb = g_lp + (size_t)t * L_ * 64;

#pragma unroll
        for (int i = 0; i < 2; i++)
#pragma unroll
            for (int j = 0; j < 4; j++)
#pragma unroll
                for (int q = 0; q < 4; q++) acc[i][j][q] = 0.0f;

        auto issue3 = [&](int kt, int buf) {
#pragma unroll
            for (int i = 0; i < 2; i++) {
                int e = tid + i * 256;
                int row = e >> 4, ch = e & 15;
                cp16(&Bs0[buf * MS_BS + row * 68 + ch * 4],
                     &lpb[(size_t)(kt * 32 + row) * 64 + ch * 4]);
            }
            CP_COMMIT();
        };

        issue3(0, 0);
        issue3(1, 1);
#pragma unroll 1
        for (int kt = 0; kt < 16; kt++) {
            const int buf = kt % 3;
            if (kt == 15) { CP_WAIT0(); } else { CP_WAIT1(); }
            __syncthreads();

#pragma unroll
            for (int kh = 0; kh < 2; kh++) {
                const int kbA = kt * 16 + kh * 8;
                unsigned a0[4], a1[4], bA[4], bB[4];
                unsigned sa = s_uni + ((warp_m * 32 + arow) * 260 + kbA + apcol) * 4;
                ldsm4(a0, sa);
                ldsm4(a1, sa + 16 * 260 * 4);
                unsigned sb = s_bs + (buf * MS_BS + (kh * 16 + bkrow) * 68) * 4 + bncol * 2;
                ldsm4t(bA, sb);
                ldsm4t(bB, sb + 32);
                mma_bf16(acc[0][0], a0, bA); mma_bf16(acc[0][1], a0, bA + 2);
                mma_bf16(acc[0][2], a0, bB); mma_bf16(acc[0][3], a0, bB + 2);
                mma_bf16(acc[1][0], a1, bA); mma_bf16(acc[1][1], a1, bA + 2);
                mma_bf16(acc[1][2], a1, bB); mma_bf16(acc[1][3], a1, bB + 2);
            }
            if (kt + 2 < 16) issue3(kt + 2, (kt + 2) % 3);
        }

        float* pb = g_part + (size_t)t * B_ * C_;
#pragma unroll
        for (int im = 0; im < 2; im++) {
#pragma unroll
            for (int half = 0; half < 2; half++) {
                int r = warp_m * 32 + im * 16 + half * 8 + lq;
#pragma unroll
                for (int jn = 0; jn < 4; jn++) {
                    int c = warp_n * 32 + jn * 8 + lr * 2;
                    if (c >= C_) continue;
                    *reinterpret_cast<float2*>(&pb[(size_t)(b0 + r) * C_ + c]) =
                        make_float2(acc[im][jn][half * 2 + 0], acc[im][jn][half * 2 + 1]);
                }
            }
        }
    }
}

// ---------------------------------------------------------------------------
// Deterministic reduction over trees + final log, float4-vectorized.
// ---------------------------------------------------------------------------
__global__ __launch_bounds__(256) void reduce_log_kernel(float* __restrict__ out) {
    const int c = (blockIdx.x * 256 + threadIdx.x) * 4;   // 0 .. B*C-4
    float4 s = make_float4(0.f, 0.f, 0.f, 0.f);
#pragma unroll
    for (int ks = 0; ks < KSPLIT; ks++) {
        float4 v = *reinterpret_cast<const float4*>(&g_part[(size_t)ks * B_ * C_ + c]);
        s.x += v.x; s.y += v.y; s.z += v.z; s.w += v.w;
    }
    const float sc = 1.0f / (float)(L_ * T_);
    float4 r;
    r.x = logf(s.x * sc); r.y = logf(s.y * sc);
    r.z = logf(s.z * sc); r.w = logf(s.w * sc);
    *reinterpret_cast<float4*>(&out[c]) = r;
}

extern "C" void kernel_launch(void* const* d_in, const int* in_sizes, int n_in,
                              void* d_out, int out_size) {
    const float* feat = (const float*)d_in[0];
    const float* W1 = (const float*)d_in[1];
    const float* b1 = (const float*)d_in[2];
    const float* W2 = (const float*)d_in[3];
    const float* b2 = (const float*)d_in[4];
    const float* pi = (const float*)d_in[5];
    float* out = (float*)d_out;

    cudaFuncSetAttribute(forest_fused, cudaFuncAttributeMaxDynamicSharedMemorySize, SMEM_BYTES);

    prep_kernel<<<2304, 256>>>(feat, W1, W2, pi);
    forest_fused<<<dim3(B_ / 64, T_), 256, SMEM_BYTES>>>(b1, b2);
    reduce_log_kernel<<<(B_ * C_) / 1024, 256>>>(out);
}